// round 1
// baseline (speedup 1.0000x reference)
#include <cuda_runtime.h>

#define BSZ 2
#define QLEN 1024
#define MLEN 1024
#define KLEN 2048
#define DM 1024
#define NH 16
#define DH 64
#define SCALE 0.125f
#define NEG_BIG (-1e30f)

// ---------------- scratch (static __device__, no allocations) ----------------
__device__ float g_kin[(size_t)BSZ * KLEN * DM];          // concat(mem, x)
__device__ float g_qw [(size_t)BSZ * QLEN * DM];          // q + r_w_bias
__device__ float g_qr [(size_t)BSZ * QLEN * DM];          // q + r_r_bias
__device__ float g_kp [(size_t)BSZ * KLEN * DM];          // k proj
__device__ float g_vp [(size_t)BSZ * KLEN * DM];          // v proj
__device__ float g_rp [(size_t)KLEN * DM];                // r proj
__device__ float g_bd [(size_t)BSZ * NH * QLEN * KLEN];   // BD (pre-shift)
__device__ float g_sc [(size_t)BSZ * NH * QLEN * KLEN];   // scores / probs
__device__ float g_av [(size_t)BSZ * QLEN * DM];          // attn_vec

// ---------------- concat(mem, x) -> kin ----------------
__global__ __launch_bounds__(256) void k_concat(const float* __restrict__ x,
                                                const float* __restrict__ mem)
{
    size_t f = ((size_t)blockIdx.x * 256 + threadIdx.x) * 4;
    size_t per_b = (size_t)KLEN * DM;
    int b = (int)(f / per_b);
    size_t rem = f - (size_t)b * per_b;
    int j = (int)(rem / DM);
    int e = (int)(rem - (size_t)j * DM);
    float4 val;
    if (j < MLEN)
        val = *(const float4*)(mem + (size_t)b * MLEN * DM + (size_t)j * DM + e);
    else
        val = *(const float4*)(x + (size_t)b * QLEN * DM + (size_t)(j - MLEN) * DM + e);
    *(float4*)(g_kin + f) = val;
}

// ---------------- 128x128x8 fp32 NT gemm core ----------------
// C[m,n] = sum_k A[m,k] * B[n,k]; 256 threads; 8x8 microtile per thread.
__device__ __forceinline__ void gemm128_core(const float* __restrict__ A, int lda,
                                             const float* __restrict__ B, int ldb,
                                             int K, float acc[8][8],
                                             float As[8][128], float Bs[8][128])
{
    const int tid = threadIdx.x;
    const int ar = tid >> 1;            // 0..127 tile row
    const int ac = (tid & 1) << 2;      // 0 or 4
    const int tx = tid & 15;
    const int ty = tid >> 4;
    const float* Arow = A + (size_t)ar * lda + ac;
    const float* Brow = B + (size_t)ar * ldb + ac;
    for (int k0 = 0; k0 < K; k0 += 8) {
        float4 a4 = *(const float4*)(Arow + k0);
        float4 b4 = *(const float4*)(Brow + k0);
        __syncthreads();
        As[ac + 0][ar] = a4.x; As[ac + 1][ar] = a4.y;
        As[ac + 2][ar] = a4.z; As[ac + 3][ar] = a4.w;
        Bs[ac + 0][ar] = b4.x; Bs[ac + 1][ar] = b4.y;
        Bs[ac + 2][ar] = b4.z; Bs[ac + 3][ar] = b4.w;
        __syncthreads();
#pragma unroll
        for (int kk = 0; kk < 8; kk++) {
            float4 a0 = *(const float4*)&As[kk][ty * 4];
            float4 a1 = *(const float4*)&As[kk][64 + ty * 4];
            float4 b0 = *(const float4*)&Bs[kk][tx * 4];
            float4 b1 = *(const float4*)&Bs[kk][64 + tx * 4];
            float ra[8] = {a0.x, a0.y, a0.z, a0.w, a1.x, a1.y, a1.z, a1.w};
            float rb[8] = {b0.x, b0.y, b0.z, b0.w, b1.x, b1.y, b1.z, b1.w};
#pragma unroll
            for (int i = 0; i < 8; i++)
#pragma unroll
                for (int jj = 0; jj < 8; jj++)
                    acc[i][jj] = fmaf(ra[i], rb[jj], acc[i][jj]);
        }
    }
}

// ---------------- plain NT gemm ----------------
__global__ __launch_bounds__(256) void k_gemm_nt(const float* __restrict__ A,
                                                 const float* __restrict__ B,
                                                 float* __restrict__ C,
                                                 int K, int lda, int ldb, int ldc)
{
    __shared__ float As[8][128], Bs[8][128];
    float acc[8][8];
#pragma unroll
    for (int i = 0; i < 8; i++)
#pragma unroll
        for (int j = 0; j < 8; j++) acc[i][j] = 0.f;
    const float* At = A + (size_t)blockIdx.y * 128 * lda;
    const float* Bt = B + (size_t)blockIdx.x * 128 * ldb;
    gemm128_core(At, lda, Bt, ldb, K, acc, As, Bs);
    const int tx = threadIdx.x & 15, ty = threadIdx.x >> 4;
    size_t m0 = (size_t)blockIdx.y * 128;
    size_t n0 = (size_t)blockIdx.x * 128;
#pragma unroll
    for (int ig = 0; ig < 2; ig++)
#pragma unroll
        for (int i = 0; i < 4; i++) {
            size_t m = m0 + ig * 64 + ty * 4 + i;
#pragma unroll
            for (int jg = 0; jg < 2; jg++) {
                float4 o = make_float4(acc[ig * 4 + i][jg * 4 + 0], acc[ig * 4 + i][jg * 4 + 1],
                                       acc[ig * 4 + i][jg * 4 + 2], acc[ig * 4 + i][jg * 4 + 3]);
                *(float4*)(C + m * ldc + n0 + jg * 64 + tx * 4) = o;
            }
        }
}

// ---------------- q projection with two bias epilogues -> g_qw, g_qr ----------------
__global__ __launch_bounds__(256) void k_gemm_qproj(const float* __restrict__ x,
                                                    const float* __restrict__ Wq,
                                                    const float* __restrict__ bw,
                                                    const float* __restrict__ br)
{
    __shared__ float As[8][128], Bs[8][128];
    float acc[8][8];
#pragma unroll
    for (int i = 0; i < 8; i++)
#pragma unroll
        for (int j = 0; j < 8; j++) acc[i][j] = 0.f;
    const float* At = x + (size_t)blockIdx.y * 128 * DM;
    const float* Bt = Wq + (size_t)blockIdx.x * 128 * DM;
    gemm128_core(At, DM, Bt, DM, DM, acc, As, Bs);
    const int tx = threadIdx.x & 15, ty = threadIdx.x >> 4;
    size_t m0 = (size_t)blockIdx.y * 128;
    size_t n0 = (size_t)blockIdx.x * 128;
#pragma unroll
    for (int ig = 0; ig < 2; ig++)
#pragma unroll
        for (int i = 0; i < 4; i++) {
            size_t m = m0 + ig * 64 + ty * 4 + i;
#pragma unroll
            for (int jg = 0; jg < 2; jg++) {
                size_t n = n0 + jg * 64 + tx * 4;
                float4 w4 = *(const float4*)(bw + n);
                float4 r4 = *(const float4*)(br + n);
                float a0 = acc[ig * 4 + i][jg * 4 + 0];
                float a1 = acc[ig * 4 + i][jg * 4 + 1];
                float a2 = acc[ig * 4 + i][jg * 4 + 2];
                float a3 = acc[ig * 4 + i][jg * 4 + 3];
                *(float4*)(g_qw + m * DM + n) = make_float4(a0 + w4.x, a1 + w4.y, a2 + w4.z, a3 + w4.w);
                *(float4*)(g_qr + m * DM + n) = make_float4(a0 + r4.x, a1 + r4.y, a2 + r4.z, a3 + r4.w);
            }
        }
}

// ---------------- BD = qr . r (batched over b,h) ----------------
__global__ __launch_bounds__(256) void k_gemm_bd()
{
    __shared__ float As[8][128], Bs[8][128];
    float acc[8][8];
#pragma unroll
    for (int i = 0; i < 8; i++)
#pragma unroll
        for (int j = 0; j < 8; j++) acc[i][j] = 0.f;
    int z = blockIdx.z, b = z >> 4, h = z & 15;
    const float* A = g_qr + (size_t)b * QLEN * DM + h * DH + (size_t)blockIdx.y * 128 * DM;
    const float* B = g_rp + h * DH + (size_t)blockIdx.x * 128 * DM;
    float* C = g_bd + (size_t)z * QLEN * KLEN;
    gemm128_core(A, DM, B, DM, DH, acc, As, Bs);
    const int tx = threadIdx.x & 15, ty = threadIdx.x >> 4;
    size_t m0 = (size_t)blockIdx.y * 128;
    size_t n0 = (size_t)blockIdx.x * 128;
#pragma unroll
    for (int ig = 0; ig < 2; ig++)
#pragma unroll
        for (int i = 0; i < 4; i++) {
            size_t m = m0 + ig * 64 + ty * 4 + i;
#pragma unroll
            for (int jg = 0; jg < 2; jg++) {
                float4 o = make_float4(acc[ig * 4 + i][jg * 4 + 0], acc[ig * 4 + i][jg * 4 + 1],
                                       acc[ig * 4 + i][jg * 4 + 2], acc[ig * 4 + i][jg * 4 + 3]);
                *(float4*)(C + m * KLEN + n0 + jg * 64 + tx * 4) = o;
            }
        }
}

// ---------------- scores = (qw.k + shifted BD) * scale, masked ----------------
__global__ __launch_bounds__(256) void k_gemm_score()
{
    __shared__ float As[8][128], Bs[8][128];
    float acc[8][8];
#pragma unroll
    for (int i = 0; i < 8; i++)
#pragma unroll
        for (int j = 0; j < 8; j++) acc[i][j] = 0.f;
    int z = blockIdx.z, b = z >> 4, h = z & 15;
    const float* A = g_qw + (size_t)b * QLEN * DM + h * DH + (size_t)blockIdx.y * 128 * DM;
    const float* B = g_kp + (size_t)b * KLEN * DM + h * DH + (size_t)blockIdx.x * 128 * DM;
    const float* bd = g_bd + (size_t)z * QLEN * KLEN;
    float* S = g_sc + (size_t)z * QLEN * KLEN;
    gemm128_core(A, DM, B, DM, DH, acc, As, Bs);
    const int tx = threadIdx.x & 15, ty = threadIdx.x >> 4;
    int m0 = blockIdx.y * 128;
    int n0 = blockIdx.x * 128;
#pragma unroll
    for (int ig = 0; ig < 2; ig++)
#pragma unroll
        for (int i = 0; i < 4; i++) {
            int m = m0 + ig * 64 + ty * 4 + i;           // query index i
#pragma unroll
            for (int jg = 0; jg < 2; jg++) {
                int jbase = n0 + jg * 64 + tx * 4;       // key index j
                float o[4];
#pragma unroll
                for (int c = 0; c < 4; c++) {
                    int j = jbase + c;
                    if (j <= m + MLEN) {
                        float bdv = bd[(size_t)m * KLEN + (j + (QLEN - 1) - m)];
                        o[c] = (acc[ig * 4 + i][jg * 4 + c] + bdv) * SCALE;
                    } else {
                        o[c] = NEG_BIG;
                    }
                }
                *(float4*)(S + (size_t)m * KLEN + jbase) = make_float4(o[0], o[1], o[2], o[3]);
            }
        }
}

// ---------------- row softmax over g_sc (in place) ----------------
__global__ __launch_bounds__(256) void k_softmax()
{
    float* p = g_sc + (size_t)blockIdx.x * KLEN;
    int tid = threadIdx.x;
    float v[8];
    float mx = NEG_BIG;
#pragma unroll
    for (int k = 0; k < 8; k++) {
        v[k] = p[tid + (k << 8)];
        mx = fmaxf(mx, v[k]);
    }
    __shared__ float red[8];
#pragma unroll
    for (int o = 16; o > 0; o >>= 1) mx = fmaxf(mx, __shfl_xor_sync(0xffffffffu, mx, o));
    if ((tid & 31) == 0) red[tid >> 5] = mx;
    __syncthreads();
    mx = red[0];
#pragma unroll
    for (int w = 1; w < 8; w++) mx = fmaxf(mx, red[w]);
    float sum = 0.f;
#pragma unroll
    for (int k = 0; k < 8; k++) {
        v[k] = __expf(v[k] - mx);
        sum += v[k];
    }
#pragma unroll
    for (int o = 16; o > 0; o >>= 1) sum += __shfl_xor_sync(0xffffffffu, sum, o);
    __syncthreads();
    if ((tid & 31) == 0) red[tid >> 5] = sum;
    __syncthreads();
    sum = 0.f;
#pragma unroll
    for (int w = 0; w < 8; w++) sum += red[w];
    float inv = 1.0f / sum;
#pragma unroll
    for (int k = 0; k < 8; k++) p[tid + (k << 8)] = v[k] * inv;
}

// ---------------- attn_vec = P . V (NN gemm, BM=128, BN=64, BK=32) ----------------
__global__ __launch_bounds__(256) void k_pv()
{
    int z = blockIdx.z, b = z >> 4, h = z & 15;
    const float* P = g_sc + (size_t)z * QLEN * KLEN + (size_t)blockIdx.y * 128 * KLEN;
    const float* V = g_vp + (size_t)b * KLEN * DM + h * DH;
    float* C = g_av + (size_t)b * QLEN * DM + h * DH + (size_t)blockIdx.y * 128 * DM;

    __shared__ float Ps[32][132];   // [k][m] transposed, padded
    __shared__ float Vs[32][64];    // [k][n]
    int tid = threadIdx.x;
    int tx = tid & 15, ty = tid >> 4;
    float acc[8][4];
#pragma unroll
    for (int i = 0; i < 8; i++)
#pragma unroll
        for (int j = 0; j < 4; j++) acc[i][j] = 0.f;

    for (int k0 = 0; k0 < KLEN; k0 += 32) {
        __syncthreads();
#pragma unroll
        for (int it = 0; it < 4; it++) {
            int idx = it * 256 + tid;
            int row = idx >> 3;            // 0..127
            int c4 = (idx & 7) << 2;       // 0..28
            float4 p4 = *(const float4*)(P + (size_t)row * KLEN + k0 + c4);
            Ps[c4 + 0][row] = p4.x; Ps[c4 + 1][row] = p4.y;
            Ps[c4 + 2][row] = p4.z; Ps[c4 + 3][row] = p4.w;
        }
#pragma unroll
        for (int it = 0; it < 2; it++) {
            int idx = it * 256 + tid;
            int row = idx >> 4;            // 0..31
            int c4 = (idx & 15) << 2;      // 0..60
            *(float4*)&Vs[row][c4] = *(const float4*)(V + (size_t)(k0 + row) * DM + c4);
        }
        __syncthreads();
#pragma unroll
        for (int kk = 0; kk < 32; kk++) {
            float4 a0 = *(const float4*)&Ps[kk][ty * 4];
            float4 a1 = *(const float4*)&Ps[kk][64 + ty * 4];
            float4 b0 = *(const float4*)&Vs[kk][tx * 4];
            float ra[8] = {a0.x, a0.y, a0.z, a0.w, a1.x, a1.y, a1.z, a1.w};
            float rb[4] = {b0.x, b0.y, b0.z, b0.w};
#pragma unroll
            for (int i = 0; i < 8; i++)
#pragma unroll
                for (int j = 0; j < 4; j++)
                    acc[i][j] = fmaf(ra[i], rb[j], acc[i][j]);
        }
    }
#pragma unroll
    for (int ig = 0; ig < 2; ig++)
#pragma unroll
        for (int i = 0; i < 4; i++) {
            int m = ig * 64 + ty * 4 + i;
            float4 o = make_float4(acc[ig * 4 + i][0], acc[ig * 4 + i][1],
                                   acc[ig * 4 + i][2], acc[ig * 4 + i][3]);
            *(float4*)(C + (size_t)m * DM + tx * 4) = o;
        }
}

// ---------------- launch ----------------
extern "C" void kernel_launch(void* const* d_in, const int* in_sizes, int n_in,
                              void* d_out, int out_size)
{
    (void)in_sizes; (void)n_in; (void)out_size;
    const float* x   = (const float*)d_in[0];
    const float* mem = (const float*)d_in[1];
    const float* pos = (const float*)d_in[2];
    // d_in[3] = attn_mask (unused; mask derived analytically)
    const float* Wq  = (const float*)d_in[4];
    const float* Wk  = (const float*)d_in[5];
    const float* Wv  = (const float*)d_in[6];
    const float* Wr  = (const float*)d_in[7];
    const float* Wo  = (const float*)d_in[8];
    const float* bw  = (const float*)d_in[9];   // r_w_bias [16,64]
    const float* br  = (const float*)d_in[10];  // r_r_bias [16,64]
    float* out = (float*)d_out;

    float *kin, *kp, *vp, *rp, *av;
    cudaGetSymbolAddress((void**)&kin, g_kin);
    cudaGetSymbolAddress((void**)&kp,  g_kp);
    cudaGetSymbolAddress((void**)&vp,  g_vp);
    cudaGetSymbolAddress((void**)&rp,  g_rp);
    cudaGetSymbolAddress((void**)&av,  g_av);

    // 1. concat(mem, x) -> kin
    k_concat<<<4096, 256>>>(x, mem);
    // 2. projections
    k_gemm_nt<<<dim3(8, 32, 1), 256>>>(kin, Wk, kp, DM, DM, DM, DM);   // k  [4096x1024]
    k_gemm_nt<<<dim3(8, 32, 1), 256>>>(kin, Wv, vp, DM, DM, DM, DM);   // v  [4096x1024]
    k_gemm_qproj<<<dim3(8, 16, 1), 256>>>(x, Wq, bw, br);              // qw,qr [2048x1024]
    k_gemm_nt<<<dim3(8, 16, 1), 256>>>(pos, Wr, rp, DM, DM, DM, DM);   // r  [2048x1024]
    // 3. BD = qr . r   (batched b,h)
    k_gemm_bd<<<dim3(16, 8, 32), 256>>>();
    // 4. scores = (qw.k + shift(BD)) * scale, masked
    k_gemm_score<<<dim3(16, 8, 32), 256>>>();
    // 5. softmax rows
    k_softmax<<<BSZ * NH * QLEN, 256>>>();
    // 6. attn_vec = P.V
    k_pv<<<dim3(1, 8, 32), 256>>>();
    // 7. out = attn_vec . Wo^T
    k_gemm_nt<<<dim3(8, 16, 1), 256>>>(av, Wo, out, DM, DM, DM, DM);
}

// round 2
// speedup vs baseline: 1.8535x; 1.8535x over previous
#include <cuda_runtime.h>
#include <cstdint>

#define BSZ 2
#define QLEN 1024
#define MLEN 1024
#define KLEN 2048
#define DM 1024
#define NH 16
#define DH 64
#define SCALE 0.125f
#define NEG_BIG (-1e30f)

// ---------------- scratch (static __device__, no allocations) ----------------
__device__ float g_qw [(size_t)BSZ * QLEN * DM];          // q + r_w_bias
__device__ float g_qr [(size_t)BSZ * QLEN * DM];          // q + r_r_bias
__device__ float g_kp [(size_t)BSZ * KLEN * DM];          // k proj
__device__ float g_vp [(size_t)BSZ * KLEN * DM];          // v proj
__device__ float g_rp [(size_t)KLEN * DM];                // r proj
__device__ float g_bd [(size_t)BSZ * NH * QLEN * KLEN];   // BD (pre-shift)
__device__ float g_sc [(size_t)BSZ * NH * QLEN * KLEN];   // scores / probs
__device__ float g_av [(size_t)BSZ * QLEN * DM];          // attn_vec

// ---------------- tf32 helpers ----------------
__device__ __forceinline__ uint32_t f2tf(float f) {
    uint32_t u;
    asm("cvt.rna.tf32.f32 %0, %1;" : "=r"(u) : "f"(f));
    return u;
}

__device__ __forceinline__ void mma_tf32(float c[4],
                                         uint32_t a0, uint32_t a1, uint32_t a2, uint32_t a3,
                                         uint32_t b0, uint32_t b1) {
    asm volatile("mma.sync.aligned.m16n8k8.row.col.f32.tf32.tf32.f32 "
                 "{%0,%1,%2,%3}, {%4,%5,%6,%7}, {%8,%9}, {%0,%1,%2,%3};"
                 : "+f"(c[0]), "+f"(c[1]), "+f"(c[2]), "+f"(c[3])
                 : "r"(a0), "r"(a1), "r"(a2), "r"(a3), "r"(b0), "r"(b1));
}

#define PAD16 20   // 16 + 4 -> ld % 32 == 20, row banks hit all multiples of 4
#define PAD32 36   // 32 + 4

// ============ 128x128 block, BK=16 NT core: C = A[128,K] * B[128,K]^T =======
// 256 threads = 8 warps (2 x 4), warp tile 64x32, acc[4][4][4].
__device__ __forceinline__ void gemm16_core(const float* __restrict__ A, int lda,
                                            const float* __restrict__ B, int ldb,
                                            int nchunk, float acc[4][4][4],
                                            uint32_t As[128][PAD16], uint32_t Bs[128][PAD16])
{
    const int tid = threadIdx.x;
    const int r = tid >> 1, cb = (tid & 1) * 8;
    const int lane = tid & 31, wid = tid >> 5;
    const int wm = wid >> 2, wn = wid & 3, lr = lane >> 2, lc = lane & 3;
    const float* Ar = A + (size_t)r * lda + cb;
    const float* Br = B + (size_t)r * ldb + cb;

    float4 a0 = *(const float4*)(Ar);
    float4 a1 = *(const float4*)(Ar + 4);
    float4 b0 = *(const float4*)(Br);
    float4 b1 = *(const float4*)(Br + 4);

    for (int c = 0; c < nchunk; c++) {
        As[r][cb + 0] = f2tf(a0.x); As[r][cb + 1] = f2tf(a0.y);
        As[r][cb + 2] = f2tf(a0.z); As[r][cb + 3] = f2tf(a0.w);
        As[r][cb + 4] = f2tf(a1.x); As[r][cb + 5] = f2tf(a1.y);
        As[r][cb + 6] = f2tf(a1.z); As[r][cb + 7] = f2tf(a1.w);
        Bs[r][cb + 0] = f2tf(b0.x); Bs[r][cb + 1] = f2tf(b0.y);
        Bs[r][cb + 2] = f2tf(b0.z); Bs[r][cb + 3] = f2tf(b0.w);
        Bs[r][cb + 4] = f2tf(b1.x); Bs[r][cb + 5] = f2tf(b1.y);
        Bs[r][cb + 6] = f2tf(b1.z); Bs[r][cb + 7] = f2tf(b1.w);
        __syncthreads();
        if (c + 1 < nchunk) {
            const float* An = Ar + (size_t)(c + 1) * 16;
            const float* Bn = Br + (size_t)(c + 1) * 16;
            a0 = *(const float4*)(An); a1 = *(const float4*)(An + 4);
            b0 = *(const float4*)(Bn); b1 = *(const float4*)(Bn + 4);
        }
#pragma unroll
        for (int kk = 0; kk < 16; kk += 8) {
            uint32_t af[4][4], bf[4][2];
#pragma unroll
            for (int i = 0; i < 4; i++) {
                int row = wm * 64 + i * 16 + lr;
                af[i][0] = As[row][kk + lc];
                af[i][1] = As[row + 8][kk + lc];
                af[i][2] = As[row][kk + lc + 4];
                af[i][3] = As[row + 8][kk + lc + 4];
            }
#pragma unroll
            for (int j = 0; j < 4; j++) {
                int col = wn * 32 + j * 8 + lr;
                bf[j][0] = Bs[col][kk + lc];
                bf[j][1] = Bs[col][kk + lc + 4];
            }
#pragma unroll
            for (int i = 0; i < 4; i++)
#pragma unroll
                for (int j = 0; j < 4; j++)
                    mma_tf32(acc[i][j], af[i][0], af[i][1], af[i][2], af[i][3],
                             bf[j][0], bf[j][1]);
        }
        __syncthreads();
    }
}

__device__ __forceinline__ void store_tile(float* __restrict__ C, int ldc,
                                           float acc[4][4][4])
{
    const int lane = threadIdx.x & 31, wid = threadIdx.x >> 5;
    const int wm = wid >> 2, wn = wid & 3, lr = lane >> 2, lc = lane & 3;
#pragma unroll
    for (int i = 0; i < 4; i++)
#pragma unroll
        for (int j = 0; j < 4; j++) {
            int r0 = wm * 64 + i * 16 + lr;
            int c0 = wn * 32 + j * 8 + 2 * lc;
            *(float2*)(C + (size_t)r0 * ldc + c0) = make_float2(acc[i][j][0], acc[i][j][1]);
            *(float2*)(C + (size_t)(r0 + 8) * ldc + c0) = make_float2(acc[i][j][2], acc[i][j][3]);
        }
}

// ---------------- fused projections: q (dual-bias), k, v, r ----------------
__global__ __launch_bounds__(256) void k_proj_all(
    const float* __restrict__ x, const float* __restrict__ mem,
    const float* __restrict__ pos,
    const float* __restrict__ Wq, const float* __restrict__ Wk,
    const float* __restrict__ Wv, const float* __restrict__ Wr,
    const float* __restrict__ bw, const float* __restrict__ br)
{
    const int job = blockIdx.z;
    const int mt = blockIdx.y, nt = blockIdx.x;
    if ((job == 0 || job == 3) && mt >= 16) return;

    const float* A;
    const float* B;
    float* C = nullptr;
    if (job == 0) {
        A = x + (size_t)mt * 128 * DM;
        B = Wq;
    } else if (job == 1 || job == 2) {
        int b = mt >> 4, seg = (mt >> 3) & 1, loc = mt & 7;
        const float* src = seg ? x : mem;
        A = src + ((size_t)b * 1024 + (size_t)loc * 128) * DM;
        B = (job == 1) ? Wk : Wv;
        C = ((job == 1) ? g_kp : g_vp) + (size_t)mt * 128 * DM;
    } else {
        A = pos + (size_t)mt * 128 * DM;
        B = Wr;
        C = g_rp + (size_t)mt * 128 * DM;
    }
    B += (size_t)nt * 128 * DM;

    __shared__ uint32_t As[128][PAD16], Bs[128][PAD16];
    float acc[4][4][4];
#pragma unroll
    for (int i = 0; i < 4; i++)
#pragma unroll
        for (int j = 0; j < 4; j++)
#pragma unroll
            for (int k = 0; k < 4; k++) acc[i][j][k] = 0.f;

    gemm16_core(A, DM, B, DM, DM / 16, acc, As, Bs);

    if (job == 0) {
        const int lane = threadIdx.x & 31, wid = threadIdx.x >> 5;
        const int wm = wid >> 2, wn = wid & 3, lr = lane >> 2, lc = lane & 3;
        size_t mbase = (size_t)mt * 128;
        int nbase = nt * 128;
#pragma unroll
        for (int i = 0; i < 4; i++)
#pragma unroll
            for (int j = 0; j < 4; j++) {
                int r0 = wm * 64 + i * 16 + lr;
                int n = nbase + wn * 32 + j * 8 + 2 * lc;
                float2 wv = *(const float2*)(bw + n);
                float2 rv = *(const float2*)(br + n);
                size_t m1 = mbase + r0, m2 = m1 + 8;
                *(float2*)(g_qw + m1 * DM + n) = make_float2(acc[i][j][0] + wv.x, acc[i][j][1] + wv.y);
                *(float2*)(g_qr + m1 * DM + n) = make_float2(acc[i][j][0] + rv.x, acc[i][j][1] + rv.y);
                *(float2*)(g_qw + m2 * DM + n) = make_float2(acc[i][j][2] + wv.x, acc[i][j][3] + wv.y);
                *(float2*)(g_qr + m2 * DM + n) = make_float2(acc[i][j][2] + rv.x, acc[i][j][3] + rv.y);
            }
    } else {
        store_tile(C + nt * 128, DM, acc);
    }
}

// ---------------- BD = qr . rp^T (batched over b,h) ----------------
__global__ __launch_bounds__(256) void k_bd()
{
    const int z = blockIdx.z, b = z >> 4, h = z & 15;
    const float* A = g_qr + (size_t)b * QLEN * DM + h * DH + (size_t)blockIdx.y * 128 * DM;
    const float* B = g_rp + h * DH + (size_t)blockIdx.x * 128 * DM;
    float* C = g_bd + (size_t)z * QLEN * KLEN + (size_t)blockIdx.y * 128 * KLEN + blockIdx.x * 128;

    __shared__ uint32_t As[128][PAD16], Bs[128][PAD16];
    float acc[4][4][4];
#pragma unroll
    for (int i = 0; i < 4; i++)
#pragma unroll
        for (int j = 0; j < 4; j++)
#pragma unroll
            for (int k = 0; k < 4; k++) acc[i][j][k] = 0.f;

    gemm16_core(A, DM, B, DM, DH / 16, acc, As, Bs);
    store_tile(C, KLEN, acc);
}

// ---------------- scores = (qw.k^T + shift(BD)) * scale, masked ----------------
__global__ __launch_bounds__(256) void k_score()
{
    const int z = blockIdx.z, b = z >> 4, h = z & 15;
    const float* A = g_qw + (size_t)b * QLEN * DM + h * DH + (size_t)blockIdx.y * 128 * DM;
    const float* B = g_kp + (size_t)b * KLEN * DM + h * DH + (size_t)blockIdx.x * 128 * DM;
    const float* bd = g_bd + (size_t)z * QLEN * KLEN;
    float* S = g_sc + (size_t)z * QLEN * KLEN;

    __shared__ uint32_t As[128][PAD16], Bs[128][PAD16];
    float acc[4][4][4];
#pragma unroll
    for (int i = 0; i < 4; i++)
#pragma unroll
        for (int j = 0; j < 4; j++)
#pragma unroll
            for (int k = 0; k < 4; k++) acc[i][j][k] = 0.f;

    gemm16_core(A, DM, B, DM, DH / 16, acc, As, Bs);

    const int lane = threadIdx.x & 31, wid = threadIdx.x >> 5;
    const int wm = wid >> 2, wn = wid & 3, lr = lane >> 2, lc = lane & 3;
    const int m0 = blockIdx.y * 128, n0 = blockIdx.x * 128;
#pragma unroll
    for (int i = 0; i < 4; i++)
#pragma unroll
        for (int j = 0; j < 4; j++) {
            int r_l = wm * 64 + i * 16 + lr;
            int c_l = wn * 32 + j * 8 + 2 * lc;
#pragma unroll
            for (int rr = 0; rr < 2; rr++) {
                int m = m0 + r_l + rr * 8;
                float v0 = acc[i][j][rr * 2 + 0];
                float v1 = acc[i][j][rr * 2 + 1];
                int j0 = n0 + c_l;
                int j1 = j0 + 1;
                float o0 = (j0 <= m + MLEN)
                             ? (v0 + bd[(size_t)m * KLEN + (j0 - m + (QLEN - 1))]) * SCALE
                             : NEG_BIG;
                float o1 = (j1 <= m + MLEN)
                             ? (v1 + bd[(size_t)m * KLEN + (j1 - m + (QLEN - 1))]) * SCALE
                             : NEG_BIG;
                *(float2*)(S + (size_t)m * KLEN + j0) = make_float2(o0, o1);
            }
        }
}

// ---------------- row softmax over g_sc (in place) ----------------
__global__ __launch_bounds__(256) void k_softmax()
{
    float* p = g_sc + (size_t)blockIdx.x * KLEN;
    int tid = threadIdx.x;
    float v[8];
    float mx = NEG_BIG;
#pragma unroll
    for (int k = 0; k < 8; k++) {
        v[k] = p[tid + (k << 8)];
        mx = fmaxf(mx, v[k]);
    }
    __shared__ float red[8];
#pragma unroll
    for (int o = 16; o > 0; o >>= 1) mx = fmaxf(mx, __shfl_xor_sync(0xffffffffu, mx, o));
    if ((tid & 31) == 0) red[tid >> 5] = mx;
    __syncthreads();
    mx = red[0];
#pragma unroll
    for (int w = 1; w < 8; w++) mx = fmaxf(mx, red[w]);
    float sum = 0.f;
#pragma unroll
    for (int k = 0; k < 8; k++) {
        v[k] = __expf(v[k] - mx);
        sum += v[k];
    }
#pragma unroll
    for (int o = 16; o > 0; o >>= 1) sum += __shfl_xor_sync(0xffffffffu, sum, o);
    __syncthreads();
    if ((tid & 31) == 0) red[tid >> 5] = sum;
    __syncthreads();
    sum = 0.f;
#pragma unroll
    for (int w = 0; w < 8; w++) sum += red[w];
    float inv = 1.0f / sum;
#pragma unroll
    for (int k = 0; k < 8; k++) p[tid + (k << 8)] = v[k] * inv;
}

// ---------------- attn_vec = P . V  (128x64 tile, BK=32) ----------------
// 8 warps (4 x 2), warp tile 32x32, acc[2][4][4].
__global__ __launch_bounds__(256) void k_pv()
{
    const int z = blockIdx.z, b = z >> 4, h = z & 15;
    const float* P = g_sc + (size_t)z * QLEN * KLEN + (size_t)blockIdx.y * 128 * KLEN;
    const float* V = g_vp + (size_t)b * KLEN * DM + h * DH;
    float* C = g_av + (size_t)b * QLEN * DM + h * DH + (size_t)blockIdx.y * 128 * DM;

    __shared__ uint32_t As[128][PAD32];
    __shared__ uint32_t Bs[64][PAD32];

    const int tid = threadIdx.x;
    const int lane = tid & 31, wid = tid >> 5;
    const int wm = wid >> 1, wn = wid & 1, lr = lane >> 2, lc = lane & 3;
    const int ra = tid >> 1, ca = (tid & 1) * 16;     // A staging: row, col base
    const int kv = tid >> 3, cv = (tid & 7) * 8;      // B staging: V row, col base

    float acc[2][4][4];
#pragma unroll
    for (int i = 0; i < 2; i++)
#pragma unroll
        for (int j = 0; j < 4; j++)
#pragma unroll
            for (int k = 0; k < 4; k++) acc[i][j][k] = 0.f;

    const float* Ar = P + (size_t)ra * KLEN + ca;
    const float* Vr = V + (size_t)kv * DM + cv;

    float4 a0 = *(const float4*)(Ar);
    float4 a1 = *(const float4*)(Ar + 4);
    float4 a2 = *(const float4*)(Ar + 8);
    float4 a3 = *(const float4*)(Ar + 12);
    float4 v0 = *(const float4*)(Vr);
    float4 v1 = *(const float4*)(Vr + 4);

    const int nchunk = KLEN / 32;
    for (int c = 0; c < nchunk; c++) {
        As[ra][ca + 0] = f2tf(a0.x); As[ra][ca + 1] = f2tf(a0.y);
        As[ra][ca + 2] = f2tf(a0.z); As[ra][ca + 3] = f2tf(a0.w);
        As[ra][ca + 4] = f2tf(a1.x); As[ra][ca + 5] = f2tf(a1.y);
        As[ra][ca + 6] = f2tf(a1.z); As[ra][ca + 7] = f2tf(a1.w);
        As[ra][ca + 8] = f2tf(a2.x); As[ra][ca + 9] = f2tf(a2.y);
        As[ra][ca + 10] = f2tf(a2.z); As[ra][ca + 11] = f2tf(a2.w);
        As[ra][ca + 12] = f2tf(a3.x); As[ra][ca + 13] = f2tf(a3.y);
        As[ra][ca + 14] = f2tf(a3.z); As[ra][ca + 15] = f2tf(a3.w);
        // V transpose: Bs[n][k]
        Bs[cv + 0][kv] = f2tf(v0.x); Bs[cv + 1][kv] = f2tf(v0.y);
        Bs[cv + 2][kv] = f2tf(v0.z); Bs[cv + 3][kv] = f2tf(v0.w);
        Bs[cv + 4][kv] = f2tf(v1.x); Bs[cv + 5][kv] = f2tf(v1.y);
        Bs[cv + 6][kv] = f2tf(v1.z); Bs[cv + 7][kv] = f2tf(v1.w);
        __syncthreads();
        if (c + 1 < nchunk) {
            const float* An = Ar + (size_t)(c + 1) * 32;
            const float* Vn = Vr + (size_t)(c + 1) * 32 * DM;
            a0 = *(const float4*)(An);      a1 = *(const float4*)(An + 4);
            a2 = *(const float4*)(An + 8);  a3 = *(const float4*)(An + 12);
            v0 = *(const float4*)(Vn);      v1 = *(const float4*)(Vn + 4);
        }
#pragma unroll
        for (int kk = 0; kk < 32; kk += 8) {
            uint32_t af[2][4], bf[4][2];
#pragma unroll
            for (int i = 0; i < 2; i++) {
                int row = wm * 32 + i * 16 + lr;
                af[i][0] = As[row][kk + lc];
                af[i][1] = As[row + 8][kk + lc];
                af[i][2] = As[row][kk + lc + 4];
                af[i][3] = As[row + 8][kk + lc + 4];
            }
#pragma unroll
            for (int j = 0; j < 4; j++) {
                int col = wn * 32 + j * 8 + lr;
                bf[j][0] = Bs[col][kk + lc];
                bf[j][1] = Bs[col][kk + lc + 4];
            }
#pragma unroll
            for (int i = 0; i < 2; i++)
#pragma unroll
                for (int j = 0; j < 4; j++)
                    mma_tf32(acc[i][j], af[i][0], af[i][1], af[i][2], af[i][3],
                             bf[j][0], bf[j][1]);
        }
        __syncthreads();
    }
#pragma unroll
    for (int i = 0; i < 2; i++)
#pragma unroll
        for (int j = 0; j < 4; j++) {
            int r0 = wm * 32 + i * 16 + lr;
            int c0 = wn * 32 + j * 8 + 2 * lc;
            *(float2*)(C + (size_t)r0 * DM + c0) = make_float2(acc[i][j][0], acc[i][j][1]);
            *(float2*)(C + (size_t)(r0 + 8) * DM + c0) = make_float2(acc[i][j][2], acc[i][j][3]);
        }
}

// ---------------- out = attn_vec . Wo^T ----------------
__global__ __launch_bounds__(256) void k_out(const float* __restrict__ Wo,
                                             float* __restrict__ out)
{
    const float* A = g_av + (size_t)blockIdx.y * 128 * DM;
    const float* B = Wo + (size_t)blockIdx.x * 128 * DM;
    float* C = out + (size_t)blockIdx.y * 128 * DM + blockIdx.x * 128;

    __shared__ uint32_t As[128][PAD16], Bs[128][PAD16];
    float acc[4][4][4];
#pragma unroll
    for (int i = 0; i < 4; i++)
#pragma unroll
        for (int j = 0; j < 4; j++)
#pragma unroll
            for (int k = 0; k < 4; k++) acc[i][j][k] = 0.f;

    gemm16_core(A, DM, B, DM, DM / 16, acc, As, Bs);
    store_tile(C, DM, acc);
}

// ---------------- launch ----------------
extern "C" void kernel_launch(void* const* d_in, const int* in_sizes, int n_in,
                              void* d_out, int out_size)
{
    (void)in_sizes; (void)n_in; (void)out_size;
    const float* x   = (const float*)d_in[0];
    const float* mem = (const float*)d_in[1];
    const float* pos = (const float*)d_in[2];
    // d_in[3] = attn_mask (unused; mask derived analytically)
    const float* Wq  = (const float*)d_in[4];
    const float* Wk  = (const float*)d_in[5];
    const float* Wv  = (const float*)d_in[6];
    const float* Wr  = (const float*)d_in[7];
    const float* Wo  = (const float*)d_in[8];
    const float* bw  = (const float*)d_in[9];   // r_w_bias [16,64]
    const float* br  = (const float*)d_in[10];  // r_r_bias [16,64]
    float* out = (float*)d_out;

    // 1. all projections in one launch (q dual-bias, k, v, r)
    k_proj_all<<<dim3(8, 32, 4), 256>>>(x, mem, pos, Wq, Wk, Wv, Wr, bw, br);
    // 2. BD = qr . r^T (batched b,h)
    k_bd<<<dim3(16, 8, 32), 256>>>();
    // 3. scores = (qw.k^T + shift(BD)) * scale, masked
    k_score<<<dim3(16, 8, 32), 256>>>();
    // 4. softmax rows
    k_softmax<<<BSZ * NH * QLEN, 256>>>();
    // 5. attn_vec = P.V
    k_pv<<<dim3(1, 8, 32), 256>>>();
    // 6. out = attn_vec . Wo^T
    k_out<<<dim3(8, 16), 256>>>(Wo, out);
}

// round 3
// speedup vs baseline: 2.1445x; 1.1570x over previous
#include <cuda_runtime.h>
#include <cstdint>

#define BSZ 2
#define QLEN 1024
#define MLEN 1024
#define KLEN 2048
#define DM 1024
#define NH 16
#define DH 64
#define SCALE 0.125f
#define NEG_BIG (-1e30f)

// ---------------- scratch (static __device__, no allocations) ----------------
__device__ float g_qw [(size_t)BSZ * QLEN * DM];          // (q + r_w_bias) * SCALE
__device__ float g_qr [(size_t)BSZ * QLEN * DM];          // (q + r_r_bias) * SCALE
__device__ float g_kp [(size_t)BSZ * KLEN * DM];          // k proj
__device__ float g_vp [(size_t)BSZ * KLEN * DM];          // v proj
__device__ float g_rp [(size_t)KLEN * DM];                // r proj
__device__ float g_bd [(size_t)BSZ * NH * QLEN * KLEN];   // BD, SHIFTED: [i][j]
__device__ float g_av [(size_t)BSZ * QLEN * DM];          // attn_vec

// ---------------- tf32 helpers ----------------
__device__ __forceinline__ uint32_t f2tf(float f) {
    uint32_t u;
    asm("cvt.rna.tf32.f32 %0, %1;" : "=r"(u) : "f"(f));
    return u;
}

__device__ __forceinline__ void mma_tf32(float c[4],
                                         uint32_t a0, uint32_t a1, uint32_t a2, uint32_t a3,
                                         uint32_t b0, uint32_t b1) {
    asm volatile("mma.sync.aligned.m16n8k8.row.col.f32.tf32.tf32.f32 "
                 "{%0,%1,%2,%3}, {%4,%5,%6,%7}, {%8,%9}, {%0,%1,%2,%3};"
                 : "+f"(c[0]), "+f"(c[1]), "+f"(c[2]), "+f"(c[3])
                 : "r"(a0), "r"(a1), "r"(a2), "r"(a3), "r"(b0), "r"(b1));
}

#define PAD16 20

// ============ 128x128 block, BK=16 NT core: C = A[128,K] * B[128,K]^T =======
__device__ __forceinline__ void gemm16_core(const float* __restrict__ A, int lda,
                                            const float* __restrict__ B, int ldb,
                                            int nchunk, float acc[4][4][4],
                                            uint32_t As[128][PAD16], uint32_t Bs[128][PAD16])
{
    const int tid = threadIdx.x;
    const int r = tid >> 1, cb = (tid & 1) * 8;
    const int lane = tid & 31, wid = tid >> 5;
    const int wm = wid >> 2, wn = wid & 3, lr = lane >> 2, lc = lane & 3;
    const float* Ar = A + (size_t)r * lda + cb;
    const float* Br = B + (size_t)r * ldb + cb;

    float4 a0 = *(const float4*)(Ar);
    float4 a1 = *(const float4*)(Ar + 4);
    float4 b0 = *(const float4*)(Br);
    float4 b1 = *(const float4*)(Br + 4);

    for (int c = 0; c < nchunk; c++) {
        As[r][cb + 0] = f2tf(a0.x); As[r][cb + 1] = f2tf(a0.y);
        As[r][cb + 2] = f2tf(a0.z); As[r][cb + 3] = f2tf(a0.w);
        As[r][cb + 4] = f2tf(a1.x); As[r][cb + 5] = f2tf(a1.y);
        As[r][cb + 6] = f2tf(a1.z); As[r][cb + 7] = f2tf(a1.w);
        Bs[r][cb + 0] = f2tf(b0.x); Bs[r][cb + 1] = f2tf(b0.y);
        Bs[r][cb + 2] = f2tf(b0.z); Bs[r][cb + 3] = f2tf(b0.w);
        Bs[r][cb + 4] = f2tf(b1.x); Bs[r][cb + 5] = f2tf(b1.y);
        Bs[r][cb + 6] = f2tf(b1.z); Bs[r][cb + 7] = f2tf(b1.w);
        __syncthreads();
        if (c + 1 < nchunk) {
            const float* An = Ar + (size_t)(c + 1) * 16;
            const float* Bn = Br + (size_t)(c + 1) * 16;
            a0 = *(const float4*)(An); a1 = *(const float4*)(An + 4);
            b0 = *(const float4*)(Bn); b1 = *(const float4*)(Bn + 4);
        }
#pragma unroll
        for (int kk = 0; kk < 16; kk += 8) {
            uint32_t af[4][4], bf[4][2];
#pragma unroll
            for (int i = 0; i < 4; i++) {
                int row = wm * 64 + i * 16 + lr;
                af[i][0] = As[row][kk + lc];
                af[i][1] = As[row + 8][kk + lc];
                af[i][2] = As[row][kk + lc + 4];
                af[i][3] = As[row + 8][kk + lc + 4];
            }
#pragma unroll
            for (int j = 0; j < 4; j++) {
                int col = wn * 32 + j * 8 + lr;
                bf[j][0] = Bs[col][kk + lc];
                bf[j][1] = Bs[col][kk + lc + 4];
            }
#pragma unroll
            for (int i = 0; i < 4; i++)
#pragma unroll
                for (int j = 0; j < 4; j++)
                    mma_tf32(acc[i][j], af[i][0], af[i][1], af[i][2], af[i][3],
                             bf[j][0], bf[j][1]);
        }
        __syncthreads();
    }
}

__device__ __forceinline__ void store_tile(float* __restrict__ C, int ldc,
                                           float acc[4][4][4])
{
    const int lane = threadIdx.x & 31, wid = threadIdx.x >> 5;
    const int wm = wid >> 2, wn = wid & 3, lr = lane >> 2, lc = lane & 3;
#pragma unroll
    for (int i = 0; i < 4; i++)
#pragma unroll
        for (int j = 0; j < 4; j++) {
            int r0 = wm * 64 + i * 16 + lr;
            int c0 = wn * 32 + j * 8 + 2 * lc;
            *(float2*)(C + (size_t)r0 * ldc + c0) = make_float2(acc[i][j][0], acc[i][j][1]);
            *(float2*)(C + (size_t)(r0 + 8) * ldc + c0) = make_float2(acc[i][j][2], acc[i][j][3]);
        }
}

// ---------------- fused projections: q (dual-bias, pre-scaled), k, v, r ------
__global__ __launch_bounds__(256) void k_proj_all(
    const float* __restrict__ x, const float* __restrict__ mem,
    const float* __restrict__ pos,
    const float* __restrict__ Wq, const float* __restrict__ Wk,
    const float* __restrict__ Wv, const float* __restrict__ Wr,
    const float* __restrict__ bw, const float* __restrict__ br)
{
    const int job = blockIdx.z;
    const int mt = blockIdx.y, nt = blockIdx.x;
    if ((job == 0 || job == 3) && mt >= 16) return;

    const float* A;
    const float* B;
    float* C = nullptr;
    if (job == 0) {
        A = x + (size_t)mt * 128 * DM;
        B = Wq;
    } else if (job == 1 || job == 2) {
        int b = mt >> 4, seg = (mt >> 3) & 1, loc = mt & 7;
        const float* src = seg ? x : mem;
        A = src + ((size_t)b * 1024 + (size_t)loc * 128) * DM;
        B = (job == 1) ? Wk : Wv;
        C = ((job == 1) ? g_kp : g_vp) + (size_t)mt * 128 * DM;
    } else {
        A = pos + (size_t)mt * 128 * DM;
        B = Wr;
        C = g_rp + (size_t)mt * 128 * DM;
    }
    B += (size_t)nt * 128 * DM;

    __shared__ uint32_t As[128][PAD16], Bs[128][PAD16];
    float acc[4][4][4];
#pragma unroll
    for (int i = 0; i < 4; i++)
#pragma unroll
        for (int j = 0; j < 4; j++)
#pragma unroll
            for (int k = 0; k < 4; k++) acc[i][j][k] = 0.f;

    gemm16_core(A, DM, B, DM, DM / 16, acc, As, Bs);

    if (job == 0) {
        const int lane = threadIdx.x & 31, wid = threadIdx.x >> 5;
        const int wm = wid >> 2, wn = wid & 3, lr = lane >> 2, lc = lane & 3;
        size_t mbase = (size_t)mt * 128;
        int nbase = nt * 128;
#pragma unroll
        for (int i = 0; i < 4; i++)
#pragma unroll
            for (int j = 0; j < 4; j++) {
                int r0 = wm * 64 + i * 16 + lr;
                int n = nbase + wn * 32 + j * 8 + 2 * lc;
                float2 wv = *(const float2*)(bw + n);
                float2 rv = *(const float2*)(br + n);
                size_t m1 = mbase + r0, m2 = m1 + 8;
                *(float2*)(g_qw + m1 * DM + n) =
                    make_float2((acc[i][j][0] + wv.x) * SCALE, (acc[i][j][1] + wv.y) * SCALE);
                *(float2*)(g_qr + m1 * DM + n) =
                    make_float2((acc[i][j][0] + rv.x) * SCALE, (acc[i][j][1] + rv.y) * SCALE);
                *(float2*)(g_qw + m2 * DM + n) =
                    make_float2((acc[i][j][2] + wv.x) * SCALE, (acc[i][j][3] + wv.y) * SCALE);
                *(float2*)(g_qr + m2 * DM + n) =
                    make_float2((acc[i][j][2] + rv.x) * SCALE, (acc[i][j][3] + rv.y) * SCALE);
            }
    } else {
        store_tile(C + nt * 128, DM, acc);
    }
}

// ---------------- BD = qr . rp^T, stored SHIFTED: bd[i][j] = BDpre[i][j-i+1023]
__global__ __launch_bounds__(256) void k_bd()
{
    if (blockIdx.x + blockIdx.y <= 6) return;   // tile entirely below j=0 band
    const int z = blockIdx.z, b = z >> 4, h = z & 15;
    const int m0 = blockIdx.y * 128, t0 = blockIdx.x * 128;
    const float* A = g_qr + (size_t)b * QLEN * DM + h * DH + (size_t)m0 * DM;
    const float* B = g_rp + h * DH + (size_t)t0 * DM;
    float* C = g_bd + (size_t)z * QLEN * KLEN;

    __shared__ uint32_t As[128][PAD16], Bs[128][PAD16];
    float acc[4][4][4];
#pragma unroll
    for (int i = 0; i < 4; i++)
#pragma unroll
        for (int j = 0; j < 4; j++)
#pragma unroll
            for (int k = 0; k < 4; k++) acc[i][j][k] = 0.f;

    gemm16_core(A, DM, B, DM, DH / 16, acc, As, Bs);

    const int lane = threadIdx.x & 31, wid = threadIdx.x >> 5;
    const int wm = wid >> 2, wn = wid & 3, lr = lane >> 2, lc = lane & 3;
#pragma unroll
    for (int i = 0; i < 4; i++)
#pragma unroll
        for (int j = 0; j < 4; j++) {
            int r0 = wm * 64 + i * 16 + lr;
            int c0 = wn * 32 + j * 8 + 2 * lc;
#pragma unroll
            for (int rr = 0; rr < 2; rr++) {
                int m = m0 + r0 + rr * 8;
                int base = c0 + t0 + m - 1023;      // shifted column j for t=c0
#pragma unroll
                for (int cc = 0; cc < 2; cc++) {
                    int jj = base + cc;
                    if (jj >= 0)
                        C[(size_t)m * KLEN + jj] = acc[i][j][rr * 2 + cc];
                }
            }
        }
}

// ---------------- fused flash: score + softmax + PV ----------------
// grid (8 qtiles, 32 bh); 256 threads, warp w owns q-rows w*16..w*16+15.
#define QW_OFF 0
#define KS_OFF 8704
#define VS_OFF (8704 + 4352)
#define PS_OFF (8704 + 4352 + 4608)
#define FLASH_SMEM ((8704 + 4352 + 4608 + 8704) * 4)

__global__ __launch_bounds__(256, 2) void k_flash()
{
    extern __shared__ uint32_t sh[];
    uint32_t* qw_s = sh + QW_OFF;   // [128][68]
    uint32_t* Ks   = sh + KS_OFF;   // [64][68]   (row j, col d)
    uint32_t* Vs   = sh + VS_OFF;   // [64][72]   (row j, col d)
    uint32_t* Ps   = sh + PS_OFF;   // [128][68]  (row i, col j_local)

    const int yq = blockIdx.x, z = blockIdx.y;
    const int b = z >> 4, h = z & 15;
    const int m0 = yq * 128;
    const int tid = threadIdx.x, lane = tid & 31, w = tid >> 5;
    const int lr = lane >> 2, lc = lane & 3;

    const float* qwp = g_qw + ((size_t)b * QLEN + m0) * DM + h * DH;
    const float* kpp = g_kp + (size_t)b * KLEN * DM + h * DH;
    const float* vpp = g_vp + (size_t)b * KLEN * DM + h * DH;
    const float* bd  = g_bd + (size_t)z * QLEN * KLEN;

    // load qw tile 128x64 (tf32)
    {
        int r = tid >> 1, cb0 = (tid & 1) * 32;
        const float* src = qwp + (size_t)r * DM + cb0;
#pragma unroll
        for (int c = 0; c < 32; c += 4) {
            float4 v = *(const float4*)(src + c);
            qw_s[r * 68 + cb0 + c + 0] = f2tf(v.x);
            qw_s[r * 68 + cb0 + c + 1] = f2tf(v.y);
            qw_s[r * 68 + cb0 + c + 2] = f2tf(v.z);
            qw_s[r * 68 + cb0 + c + 3] = f2tf(v.w);
        }
    }

    float mst0 = NEG_BIG, mst1 = NEG_BIG, lst0 = 0.f, lst1 = 0.f;
    float o[8][4];
#pragma unroll
    for (int j = 0; j < 8; j++)
#pragma unroll
        for (int k = 0; k < 4; k++) o[j][k] = 0.f;

    const int nsteps = 2 * yq + 18;
    const int kr = tid >> 2, kcb = (tid & 3) * 16;   // staging: row, col base
    const int i0 = m0 + w * 16 + lr, i1 = i0 + 8;
    const int arow0 = (w * 16 + lr) * 68, arow1 = arow0 + 8 * 68;

    float4 kreg[4], vreg[4];
    {
        const float* ks = kpp + (size_t)kr * DM + kcb;
        const float* vs = vpp + (size_t)kr * DM + kcb;
#pragma unroll
        for (int c = 0; c < 4; c++) {
            kreg[c] = *(const float4*)(ks + c * 4);
            vreg[c] = *(const float4*)(vs + c * 4);
        }
    }

    for (int s = 0; s < nsteps; s++) {
        const int n0 = s * 64;
        __syncthreads();
#pragma unroll
        for (int c = 0; c < 4; c++) {
            int cb = kcb + c * 4;
            Ks[kr * 68 + cb + 0] = f2tf(kreg[c].x);
            Ks[kr * 68 + cb + 1] = f2tf(kreg[c].y);
            Ks[kr * 68 + cb + 2] = f2tf(kreg[c].z);
            Ks[kr * 68 + cb + 3] = f2tf(kreg[c].w);
            Vs[kr * 72 + cb + 0] = f2tf(vreg[c].x);
            Vs[kr * 72 + cb + 1] = f2tf(vreg[c].y);
            Vs[kr * 72 + cb + 2] = f2tf(vreg[c].z);
            Vs[kr * 72 + cb + 3] = f2tf(vreg[c].w);
        }
        __syncthreads();
        if (s + 1 < nsteps) {
            const float* ks = kpp + (size_t)(n0 + 64 + kr) * DM + kcb;
            const float* vs = vpp + (size_t)(n0 + 64 + kr) * DM + kcb;
#pragma unroll
            for (int c = 0; c < 4; c++) {
                kreg[c] = *(const float4*)(ks + c * 4);
                vreg[c] = *(const float4*)(vs + c * 4);
            }
        }

        // ---- score MMA: sacc[j][4] = qw(16 rows) x K(64 cols) ----
        float sacc[8][4];
#pragma unroll
        for (int j = 0; j < 8; j++)
#pragma unroll
            for (int k = 0; k < 4; k++) sacc[j][k] = 0.f;
#pragma unroll
        for (int kk = 0; kk < 64; kk += 8) {
            uint32_t a0 = qw_s[arow0 + kk + lc];
            uint32_t a1 = qw_s[arow1 + kk + lc];
            uint32_t a2 = qw_s[arow0 + kk + lc + 4];
            uint32_t a3 = qw_s[arow1 + kk + lc + 4];
#pragma unroll
            for (int j = 0; j < 8; j++) {
                uint32_t b0 = Ks[(j * 8 + lr) * 68 + kk + lc];
                uint32_t b1 = Ks[(j * 8 + lr) * 68 + kk + lc + 4];
                mma_tf32(sacc[j], a0, a1, a2, a3, b0, b1);
            }
        }

        // ---- add BD (pre-shifted, pre-scaled) + mask ----
#pragma unroll
        for (int j = 0; j < 8; j++) {
            int jc = n0 + j * 8 + 2 * lc;
            sacc[j][0] = (jc     <= i0 + MLEN) ? sacc[j][0] + bd[(size_t)i0 * KLEN + jc]     : NEG_BIG;
            sacc[j][1] = (jc + 1 <= i0 + MLEN) ? sacc[j][1] + bd[(size_t)i0 * KLEN + jc + 1] : NEG_BIG;
            sacc[j][2] = (jc     <= i1 + MLEN) ? sacc[j][2] + bd[(size_t)i1 * KLEN + jc]     : NEG_BIG;
            sacc[j][3] = (jc + 1 <= i1 + MLEN) ? sacc[j][3] + bd[(size_t)i1 * KLEN + jc + 1] : NEG_BIG;
        }

        // ---- online softmax (rows i0, i1; reduce over quad lanes) ----
        float mx0 = NEG_BIG, mx1 = NEG_BIG;
#pragma unroll
        for (int j = 0; j < 8; j++) {
            mx0 = fmaxf(mx0, fmaxf(sacc[j][0], sacc[j][1]));
            mx1 = fmaxf(mx1, fmaxf(sacc[j][2], sacc[j][3]));
        }
        mx0 = fmaxf(mx0, __shfl_xor_sync(0xffffffffu, mx0, 1));
        mx0 = fmaxf(mx0, __shfl_xor_sync(0xffffffffu, mx0, 2));
        mx1 = fmaxf(mx1, __shfl_xor_sync(0xffffffffu, mx1, 1));
        mx1 = fmaxf(mx1, __shfl_xor_sync(0xffffffffu, mx1, 2));
        float mn0 = fmaxf(mst0, mx0), mn1 = fmaxf(mst1, mx1);
        float f0 = __expf(mst0 - mn0), f1 = __expf(mst1 - mn1);
        float sum0 = 0.f, sum1 = 0.f;
        int prow0 = arow0, prow1 = arow1;
#pragma unroll
        for (int j = 0; j < 8; j++) {
            int cb = j * 8 + 2 * lc;
            float p0 = __expf(sacc[j][0] - mn0);
            float p1 = __expf(sacc[j][1] - mn0);
            float p2 = __expf(sacc[j][2] - mn1);
            float p3 = __expf(sacc[j][3] - mn1);
            sum0 += p0 + p1; sum1 += p2 + p3;
            Ps[prow0 + cb] = f2tf(p0); Ps[prow0 + cb + 1] = f2tf(p1);
            Ps[prow1 + cb] = f2tf(p2); Ps[prow1 + cb + 1] = f2tf(p3);
        }
        sum0 += __shfl_xor_sync(0xffffffffu, sum0, 1);
        sum0 += __shfl_xor_sync(0xffffffffu, sum0, 2);
        sum1 += __shfl_xor_sync(0xffffffffu, sum1, 1);
        sum1 += __shfl_xor_sync(0xffffffffu, sum1, 2);
        lst0 = lst0 * f0 + sum0;  lst1 = lst1 * f1 + sum1;
        mst0 = mn0;  mst1 = mn1;
#pragma unroll
        for (int j = 0; j < 8; j++) {
            o[j][0] *= f0; o[j][1] *= f0; o[j][2] *= f1; o[j][3] *= f1;
        }
        __syncwarp();

        // ---- PV MMA: o += P(16 x 64) x V(64 x 64) ----
#pragma unroll
        for (int kk = 0; kk < 64; kk += 8) {
            uint32_t a0 = Ps[arow0 + kk + lc];
            uint32_t a1 = Ps[arow1 + kk + lc];
            uint32_t a2 = Ps[arow0 + kk + lc + 4];
            uint32_t a3 = Ps[arow1 + kk + lc + 4];
#pragma unroll
            for (int jd = 0; jd < 8; jd++) {
                uint32_t b0 = Vs[(kk + lc) * 72 + jd * 8 + lr];
                uint32_t b1 = Vs[(kk + lc + 4) * 72 + jd * 8 + lr];
                mma_tf32(o[jd], a0, a1, a2, a3, b0, b1);
            }
        }
    }

    // ---- normalize and write attn_vec ----
    float inv0 = 1.0f / lst0, inv1 = 1.0f / lst1;
    float* outp = g_av + ((size_t)b * QLEN + m0) * DM + h * DH;
#pragma unroll
    for (int jd = 0; jd < 8; jd++) {
        int cb = jd * 8 + 2 * lc;
        *(float2*)(outp + (size_t)(w * 16 + lr) * DM + cb) =
            make_float2(o[jd][0] * inv0, o[jd][1] * inv0);
        *(float2*)(outp + (size_t)(w * 16 + 8 + lr) * DM + cb) =
            make_float2(o[jd][2] * inv1, o[jd][3] * inv1);
    }
}

// ---------------- out = attn_vec . Wo^T ----------------
__global__ __launch_bounds__(256) void k_out(const float* __restrict__ Wo,
                                             float* __restrict__ out)
{
    const float* A = g_av + (size_t)blockIdx.y * 128 * DM;
    const float* B = Wo + (size_t)blockIdx.x * 128 * DM;
    float* C = out + (size_t)blockIdx.y * 128 * DM + blockIdx.x * 128;

    __shared__ uint32_t As[128][PAD16], Bs[128][PAD16];
    float acc[4][4][4];
#pragma unroll
    for (int i = 0; i < 4; i++)
#pragma unroll
        for (int j = 0; j < 4; j++)
#pragma unroll
            for (int k = 0; k < 4; k++) acc[i][j][k] = 0.f;

    gemm16_core(A, DM, B, DM, DM / 16, acc, As, Bs);
    store_tile(C, DM, acc);
}

// ---------------- launch ----------------
extern "C" void kernel_launch(void* const* d_in, const int* in_sizes, int n_in,
                              void* d_out, int out_size)
{
    (void)in_sizes; (void)n_in; (void)out_size;
    const float* x   = (const float*)d_in[0];
    const float* mem = (const float*)d_in[1];
    const float* pos = (const float*)d_in[2];
    // d_in[3] = attn_mask (unused; mask derived analytically)
    const float* Wq  = (const float*)d_in[4];
    const float* Wk  = (const float*)d_in[5];
    const float* Wv  = (const float*)d_in[6];
    const float* Wr  = (const float*)d_in[7];
    const float* Wo  = (const float*)d_in[8];
    const float* bw  = (const float*)d_in[9];   // r_w_bias [16,64]
    const float* br  = (const float*)d_in[10];  // r_r_bias [16,64]
    float* out = (float*)d_out;

    static bool attr_done = false;
    if (!attr_done) {
        cudaFuncSetAttribute(k_flash, cudaFuncAttributeMaxDynamicSharedMemorySize,
                             FLASH_SMEM);
        attr_done = true;
    }

    // 1. all projections (q dual-bias pre-scaled, k, v, r)
    k_proj_all<<<dim3(8, 32, 4), 256>>>(x, mem, pos, Wq, Wk, Wv, Wr, bw, br);
    // 2. BD (shifted store, banded tiles)
    k_bd<<<dim3(16, 8, 32), 256>>>();
    // 3. fused score + softmax + PV
    k_flash<<<dim3(8, 32), 256, FLASH_SMEM>>>();
    // 4. out = attn_vec . Wo^T
    k_out<<<dim3(8, 16), 256>>>(Wo, out);
}

// round 4
// speedup vs baseline: 2.2958x; 1.0705x over previous
#include <cuda_runtime.h>
#include <cstdint>

#define BSZ 2
#define QLEN 1024
#define MLEN 1024
#define KLEN 2048
#define DM 1024
#define NH 16
#define DH 64
#define SCALE 0.125f
#define NEG_BIG (-1e30f)

// ---------------- scratch (static __device__, no allocations) ----------------
// All intermediates below are stored PRE-ROUNDED to tf32 (RNA) by their producers.
__device__ float g_qw [(size_t)BSZ * QLEN * DM];          // tf32((q + r_w_bias) * SCALE)
__device__ float g_qr [(size_t)BSZ * QLEN * DM];          // tf32((q + r_r_bias) * SCALE)
__device__ float g_kp [(size_t)BSZ * KLEN * DM];          // tf32(k proj)
__device__ float g_vp [(size_t)BSZ * KLEN * DM];          // tf32(v proj)
__device__ float g_rp [(size_t)KLEN * DM];                // tf32(r proj)
__device__ float g_bd [(size_t)BSZ * NH * QLEN * KLEN];   // BD, SHIFTED: [i][j] (f32)
__device__ float g_av [(size_t)BSZ * QLEN * DM];          // tf32(attn_vec)

// ---------------- tf32 helpers ----------------
__device__ __forceinline__ uint32_t f2tf(float f) {
    uint32_t u;
    asm("cvt.rna.tf32.f32 %0, %1;" : "=r"(u) : "f"(f));
    return u;
}
__device__ __forceinline__ float f2tf_f(float f) { return __uint_as_float(f2tf(f)); }

__device__ __forceinline__ void mma_tf32(float c[4],
                                         uint32_t a0, uint32_t a1, uint32_t a2, uint32_t a3,
                                         uint32_t b0, uint32_t b1) {
    asm volatile("mma.sync.aligned.m16n8k8.row.col.f32.tf32.tf32.f32 "
                 "{%0,%1,%2,%3}, {%4,%5,%6,%7}, {%8,%9}, {%0,%1,%2,%3};"
                 : "+f"(c[0]), "+f"(c[1]), "+f"(c[2]), "+f"(c[3])
                 : "r"(a0), "r"(a1), "r"(a2), "r"(a3), "r"(b0), "r"(b1));
}

#define PAD16 20

// ============ 128x128 block, BK=16, DOUBLE-BUFFERED NT core =================
// C = A[128,K] * B[128,K]^T; 256 threads = 8 warps (2x4), warp tile 64x32.
// One __syncthreads per chunk; LDG prefetch overlaps MMA.
template<bool CVTA, bool CVTB>
__device__ __forceinline__ void gemm_db(const float* __restrict__ A, int lda,
                                        const float* __restrict__ B, int ldb,
                                        int nchunk, float acc[4][4][4],
                                        uint32_t As[2][128][PAD16],
                                        uint32_t Bs[2][128][PAD16])
{
    const int tid = threadIdx.x;
    const int r = tid >> 1, cb = (tid & 1) * 8;
    const int lane = tid & 31, wid = tid >> 5;
    const int wm = wid >> 2, wn = wid & 3, lr = lane >> 2, lc = lane & 3;
    const float* Ar = A + (size_t)r * lda + cb;
    const float* Br = B + (size_t)r * ldb + cb;

    float4 a0 = *(const float4*)(Ar);
    float4 a1 = *(const float4*)(Ar + 4);
    float4 b0 = *(const float4*)(Br);
    float4 b1 = *(const float4*)(Br + 4);

    // stage chunk 0 -> buffer 0
    {
        uint32_t* ap = &As[0][r][cb];
        ap[0] = CVTA ? f2tf(a0.x) : __float_as_uint(a0.x);
        ap[1] = CVTA ? f2tf(a0.y) : __float_as_uint(a0.y);
        ap[2] = CVTA ? f2tf(a0.z) : __float_as_uint(a0.z);
        ap[3] = CVTA ? f2tf(a0.w) : __float_as_uint(a0.w);
        ap[4] = CVTA ? f2tf(a1.x) : __float_as_uint(a1.x);
        ap[5] = CVTA ? f2tf(a1.y) : __float_as_uint(a1.y);
        ap[6] = CVTA ? f2tf(a1.z) : __float_as_uint(a1.z);
        ap[7] = CVTA ? f2tf(a1.w) : __float_as_uint(a1.w);
        uint32_t* bp = &Bs[0][r][cb];
        bp[0] = CVTB ? f2tf(b0.x) : __float_as_uint(b0.x);
        bp[1] = CVTB ? f2tf(b0.y) : __float_as_uint(b0.y);
        bp[2] = CVTB ? f2tf(b0.z) : __float_as_uint(b0.z);
        bp[3] = CVTB ? f2tf(b0.w) : __float_as_uint(b0.w);
        bp[4] = CVTB ? f2tf(b1.x) : __float_as_uint(b1.x);
        bp[5] = CVTB ? f2tf(b1.y) : __float_as_uint(b1.y);
        bp[6] = CVTB ? f2tf(b1.z) : __float_as_uint(b1.z);
        bp[7] = CVTB ? f2tf(b1.w) : __float_as_uint(b1.w);
    }
    __syncthreads();

    for (int c = 0; c < nchunk; c++) {
        const int cur = c & 1;
        const bool more = (c + 1 < nchunk);
        if (more) {
            const float* An = Ar + (size_t)(c + 1) * 16;
            const float* Bn = Br + (size_t)(c + 1) * 16;
            a0 = *(const float4*)(An); a1 = *(const float4*)(An + 4);
            b0 = *(const float4*)(Bn); b1 = *(const float4*)(Bn + 4);
        }
#pragma unroll
        for (int kk = 0; kk < 16; kk += 8) {
            uint32_t af[4][4], bf[4][2];
#pragma unroll
            for (int i = 0; i < 4; i++) {
                int row = wm * 64 + i * 16 + lr;
                af[i][0] = As[cur][row][kk + lc];
                af[i][1] = As[cur][row + 8][kk + lc];
                af[i][2] = As[cur][row][kk + lc + 4];
                af[i][3] = As[cur][row + 8][kk + lc + 4];
            }
#pragma unroll
            for (int j = 0; j < 4; j++) {
                int col = wn * 32 + j * 8 + lr;
                bf[j][0] = Bs[cur][col][kk + lc];
                bf[j][1] = Bs[cur][col][kk + lc + 4];
            }
#pragma unroll
            for (int i = 0; i < 4; i++)
#pragma unroll
                for (int j = 0; j < 4; j++)
                    mma_tf32(acc[i][j], af[i][0], af[i][1], af[i][2], af[i][3],
                             bf[j][0], bf[j][1]);
        }
        if (more) {
            const int nxt = cur ^ 1;
            uint32_t* ap = &As[nxt][r][cb];
            ap[0] = CVTA ? f2tf(a0.x) : __float_as_uint(a0.x);
            ap[1] = CVTA ? f2tf(a0.y) : __float_as_uint(a0.y);
            ap[2] = CVTA ? f2tf(a0.z) : __float_as_uint(a0.z);
            ap[3] = CVTA ? f2tf(a0.w) : __float_as_uint(a0.w);
            ap[4] = CVTA ? f2tf(a1.x) : __float_as_uint(a1.x);
            ap[5] = CVTA ? f2tf(a1.y) : __float_as_uint(a1.y);
            ap[6] = CVTA ? f2tf(a1.z) : __float_as_uint(a1.z);
            ap[7] = CVTA ? f2tf(a1.w) : __float_as_uint(a1.w);
            uint32_t* bp = &Bs[nxt][r][cb];
            bp[0] = CVTB ? f2tf(b0.x) : __float_as_uint(b0.x);
            bp[1] = CVTB ? f2tf(b0.y) : __float_as_uint(b0.y);
            bp[2] = CVTB ? f2tf(b0.z) : __float_as_uint(b0.z);
            bp[3] = CVTB ? f2tf(b0.w) : __float_as_uint(b0.w);
            bp[4] = CVTB ? f2tf(b1.x) : __float_as_uint(b1.x);
            bp[5] = CVTB ? f2tf(b1.y) : __float_as_uint(b1.y);
            bp[6] = CVTB ? f2tf(b1.z) : __float_as_uint(b1.z);
            bp[7] = CVTB ? f2tf(b1.w) : __float_as_uint(b1.w);
            __syncthreads();
        }
    }
}

// store_tile with optional tf32 pre-rounding of the output
template<bool ROUND>
__device__ __forceinline__ void store_tile(float* __restrict__ C, int ldc,
                                           float acc[4][4][4])
{
    const int lane = threadIdx.x & 31, wid = threadIdx.x >> 5;
    const int wm = wid >> 2, wn = wid & 3, lr = lane >> 2, lc = lane & 3;
#pragma unroll
    for (int i = 0; i < 4; i++)
#pragma unroll
        for (int j = 0; j < 4; j++) {
            int r0 = wm * 64 + i * 16 + lr;
            int c0 = wn * 32 + j * 8 + 2 * lc;
            float v0 = ROUND ? f2tf_f(acc[i][j][0]) : acc[i][j][0];
            float v1 = ROUND ? f2tf_f(acc[i][j][1]) : acc[i][j][1];
            float v2 = ROUND ? f2tf_f(acc[i][j][2]) : acc[i][j][2];
            float v3 = ROUND ? f2tf_f(acc[i][j][3]) : acc[i][j][3];
            *(float2*)(C + (size_t)r0 * ldc + c0) = make_float2(v0, v1);
            *(float2*)(C + (size_t)(r0 + 8) * ldc + c0) = make_float2(v2, v3);
        }
}

// ---------------- fused projections: q (dual-bias, pre-scaled), k, v, r ------
// flat grid (8 nt, 96 y): y<16 -> q, y<48 -> k, y<80 -> v, else -> r
__global__ __launch_bounds__(256) void k_proj_all(
    const float* __restrict__ x, const float* __restrict__ mem,
    const float* __restrict__ pos,
    const float* __restrict__ Wq, const float* __restrict__ Wk,
    const float* __restrict__ Wv, const float* __restrict__ Wr,
    const float* __restrict__ bw, const float* __restrict__ br)
{
    const int y = blockIdx.y, nt = blockIdx.x;
    int job, mt;
    if (y < 16)      { job = 0; mt = y; }
    else if (y < 48) { job = 1; mt = y - 16; }
    else if (y < 80) { job = 2; mt = y - 48; }
    else             { job = 3; mt = y - 80; }

    const float* A;
    const float* B;
    float* C = nullptr;
    if (job == 0) {
        A = x + (size_t)mt * 128 * DM;
        B = Wq;
    } else if (job == 1 || job == 2) {
        int b = mt >> 4, seg = (mt >> 3) & 1, loc = mt & 7;
        const float* src = seg ? x : mem;
        A = src + ((size_t)b * 1024 + (size_t)loc * 128) * DM;
        B = (job == 1) ? Wk : Wv;
        C = ((job == 1) ? g_kp : g_vp) + (size_t)mt * 128 * DM;
    } else {
        A = pos + (size_t)mt * 128 * DM;
        B = Wr;
        C = g_rp + (size_t)mt * 128 * DM;
    }
    B += (size_t)nt * 128 * DM;

    __shared__ uint32_t As[2][128][PAD16], Bs[2][128][PAD16];
    float acc[4][4][4];
#pragma unroll
    for (int i = 0; i < 4; i++)
#pragma unroll
        for (int j = 0; j < 4; j++)
#pragma unroll
            for (int k = 0; k < 4; k++) acc[i][j][k] = 0.f;

    gemm_db<true, true>(A, DM, B, DM, DM / 16, acc, As, Bs);

    if (job == 0) {
        const int lane = threadIdx.x & 31, wid = threadIdx.x >> 5;
        const int wm = wid >> 2, wn = wid & 3, lr = lane >> 2, lc = lane & 3;
        size_t mbase = (size_t)mt * 128;
        int nbase = nt * 128;
#pragma unroll
        for (int i = 0; i < 4; i++)
#pragma unroll
            for (int j = 0; j < 4; j++) {
                int r0 = wm * 64 + i * 16 + lr;
                int n = nbase + wn * 32 + j * 8 + 2 * lc;
                float2 wv = *(const float2*)(bw + n);
                float2 rv = *(const float2*)(br + n);
                size_t m1 = mbase + r0, m2 = m1 + 8;
                *(float2*)(g_qw + m1 * DM + n) = make_float2(
                    f2tf_f((acc[i][j][0] + wv.x) * SCALE), f2tf_f((acc[i][j][1] + wv.y) * SCALE));
                *(float2*)(g_qr + m1 * DM + n) = make_float2(
                    f2tf_f((acc[i][j][0] + rv.x) * SCALE), f2tf_f((acc[i][j][1] + rv.y) * SCALE));
                *(float2*)(g_qw + m2 * DM + n) = make_float2(
                    f2tf_f((acc[i][j][2] + wv.x) * SCALE), f2tf_f((acc[i][j][3] + wv.y) * SCALE));
                *(float2*)(g_qr + m2 * DM + n) = make_float2(
                    f2tf_f((acc[i][j][2] + rv.x) * SCALE), f2tf_f((acc[i][j][3] + rv.y) * SCALE));
            }
    } else {
        store_tile<true>(C + nt * 128, DM, acc);
    }
}

// ---------------- BD = qr . rp^T, stored SHIFTED: bd[i][j] = BDpre[i][j-i+1023]
__global__ __launch_bounds__(256) void k_bd()
{
    if (blockIdx.x + blockIdx.y <= 6) return;   // tile entirely below j=0 band
    const int z = blockIdx.z, b = z >> 4, h = z & 15;
    const int m0 = blockIdx.y * 128, t0 = blockIdx.x * 128;
    const float* A = g_qr + (size_t)b * QLEN * DM + h * DH + (size_t)m0 * DM;
    const float* B = g_rp + h * DH + (size_t)t0 * DM;
    float* C = g_bd + (size_t)z * QLEN * KLEN;

    __shared__ uint32_t As[2][128][PAD16], Bs[2][128][PAD16];
    float acc[4][4][4];
#pragma unroll
    for (int i = 0; i < 4; i++)
#pragma unroll
        for (int j = 0; j < 4; j++)
#pragma unroll
            for (int k = 0; k < 4; k++) acc[i][j][k] = 0.f;

    gemm_db<false, false>(A, DM, B, DM, DH / 16, acc, As, Bs);

    const int lane = threadIdx.x & 31, wid = threadIdx.x >> 5;
    const int wm = wid >> 2, wn = wid & 3, lr = lane >> 2, lc = lane & 3;
#pragma unroll
    for (int i = 0; i < 4; i++)
#pragma unroll
        for (int j = 0; j < 4; j++) {
            int r0 = wm * 64 + i * 16 + lr;
            int c0 = wn * 32 + j * 8 + 2 * lc;
#pragma unroll
            for (int rr = 0; rr < 2; rr++) {
                int m = m0 + r0 + rr * 8;
                int base = c0 + t0 + m - 1023;      // shifted column j for t=c0
#pragma unroll
                for (int cc = 0; cc < 2; cc++) {
                    int jj = base + cc;
                    if (jj >= 0)
                        C[(size_t)m * KLEN + jj] = acc[i][j][rr * 2 + cc];
                }
            }
        }
}

// ---------------- fused flash: score + softmax + PV ----------------
// grid (8 qtiles, 32 bh); 256 threads, warp w owns q-rows w*16..w*16+15.
#define QW_OFF 0
#define KS_OFF 8704
#define VS_OFF (8704 + 4352)
#define PS_OFF (8704 + 4352 + 4608)
#define FLASH_SMEM ((8704 + 4352 + 4608 + 8704) * 4)

__global__ __launch_bounds__(256, 2) void k_flash()
{
    extern __shared__ uint32_t sh[];
    uint32_t* qw_s = sh + QW_OFF;   // [128][68]
    uint32_t* Ks   = sh + KS_OFF;   // [64][68]   (row j, col d)
    uint32_t* Vs   = sh + VS_OFF;   // [64][72]   (row j, col d)
    uint32_t* Ps   = sh + PS_OFF;   // [128][68]  (row i, col j_local)

    const int yq = blockIdx.x, z = blockIdx.y;
    const int b = z >> 4, h = z & 15;
    const int m0 = yq * 128;
    const int tid = threadIdx.x, lane = tid & 31, w = tid >> 5;
    const int lr = lane >> 2, lc = lane & 3;

    const float* qwp = g_qw + ((size_t)b * QLEN + m0) * DM + h * DH;
    const float* kpp = g_kp + (size_t)b * KLEN * DM + h * DH;
    const float* vpp = g_vp + (size_t)b * KLEN * DM + h * DH;
    const float* bd  = g_bd + (size_t)z * QLEN * KLEN;

    // load qw tile 128x64 (already tf32-rounded by producer)
    {
        int r = tid >> 1, cb0 = (tid & 1) * 32;
        const float* src = qwp + (size_t)r * DM + cb0;
#pragma unroll
        for (int c = 0; c < 32; c += 4) {
            float4 v = *(const float4*)(src + c);
            qw_s[r * 68 + cb0 + c + 0] = __float_as_uint(v.x);
            qw_s[r * 68 + cb0 + c + 1] = __float_as_uint(v.y);
            qw_s[r * 68 + cb0 + c + 2] = __float_as_uint(v.z);
            qw_s[r * 68 + cb0 + c + 3] = __float_as_uint(v.w);
        }
    }

    float mst0 = NEG_BIG, mst1 = NEG_BIG, lst0 = 0.f, lst1 = 0.f;
    float o[8][4];
#pragma unroll
    for (int j = 0; j < 8; j++)
#pragma unroll
        for (int k = 0; k < 4; k++) o[j][k] = 0.f;

    const int nsteps = 2 * yq + 18;
    const int kr = tid >> 2, kcb = (tid & 3) * 16;   // staging: row, col base
    const int i0 = m0 + w * 16 + lr, i1 = i0 + 8;
    const int arow0 = (w * 16 + lr) * 68, arow1 = arow0 + 8 * 68;

    float4 kreg[4], vreg[4];
    {
        const float* ks = kpp + (size_t)kr * DM + kcb;
        const float* vs = vpp + (size_t)kr * DM + kcb;
#pragma unroll
        for (int c = 0; c < 4; c++) {
            kreg[c] = *(const float4*)(ks + c * 4);
            vreg[c] = *(const float4*)(vs + c * 4);
        }
    }

    for (int s = 0; s < nsteps; s++) {
        const int n0 = s * 64;
        __syncthreads();
#pragma unroll
        for (int c = 0; c < 4; c++) {
            int cb = kcb + c * 4;
            Ks[kr * 68 + cb + 0] = __float_as_uint(kreg[c].x);
            Ks[kr * 68 + cb + 1] = __float_as_uint(kreg[c].y);
            Ks[kr * 68 + cb + 2] = __float_as_uint(kreg[c].z);
            Ks[kr * 68 + cb + 3] = __float_as_uint(kreg[c].w);
            Vs[kr * 72 + cb + 0] = __float_as_uint(vreg[c].x);
            Vs[kr * 72 + cb + 1] = __float_as_uint(vreg[c].y);
            Vs[kr * 72 + cb + 2] = __float_as_uint(vreg[c].z);
            Vs[kr * 72 + cb + 3] = __float_as_uint(vreg[c].w);
        }
        __syncthreads();
        if (s + 1 < nsteps) {
            const float* ks = kpp + (size_t)(n0 + 64 + kr) * DM + kcb;
            const float* vs = vpp + (size_t)(n0 + 64 + kr) * DM + kcb;
#pragma unroll
            for (int c = 0; c < 4; c++) {
                kreg[c] = *(const float4*)(ks + c * 4);
                vreg[c] = *(const float4*)(vs + c * 4);
            }
        }

        // ---- score MMA: sacc[j][4] = qw(16 rows) x K(64 cols) ----
        float sacc[8][4];
#pragma unroll
        for (int j = 0; j < 8; j++)
#pragma unroll
            for (int k = 0; k < 4; k++) sacc[j][k] = 0.f;
#pragma unroll
        for (int kk = 0; kk < 64; kk += 8) {
            uint32_t a0 = qw_s[arow0 + kk + lc];
            uint32_t a1 = qw_s[arow1 + kk + lc];
            uint32_t a2 = qw_s[arow0 + kk + lc + 4];
            uint32_t a3 = qw_s[arow1 + kk + lc + 4];
#pragma unroll
            for (int j = 0; j < 8; j++) {
                uint32_t b0 = Ks[(j * 8 + lr) * 68 + kk + lc];
                uint32_t b1 = Ks[(j * 8 + lr) * 68 + kk + lc + 4];
                mma_tf32(sacc[j], a0, a1, a2, a3, b0, b1);
            }
        }

        // ---- add BD (pre-shifted, pre-scaled) + mask ----
#pragma unroll
        for (int j = 0; j < 8; j++) {
            int jc = n0 + j * 8 + 2 * lc;
            sacc[j][0] = (jc     <= i0 + MLEN) ? sacc[j][0] + bd[(size_t)i0 * KLEN + jc]     : NEG_BIG;
            sacc[j][1] = (jc + 1 <= i0 + MLEN) ? sacc[j][1] + bd[(size_t)i0 * KLEN + jc + 1] : NEG_BIG;
            sacc[j][2] = (jc     <= i1 + MLEN) ? sacc[j][2] + bd[(size_t)i1 * KLEN + jc]     : NEG_BIG;
            sacc[j][3] = (jc + 1 <= i1 + MLEN) ? sacc[j][3] + bd[(size_t)i1 * KLEN + jc + 1] : NEG_BIG;
        }

        // ---- online softmax (rows i0, i1; reduce over quad lanes) ----
        float mx0 = NEG_BIG, mx1 = NEG_BIG;
#pragma unroll
        for (int j = 0; j < 8; j++) {
            mx0 = fmaxf(mx0, fmaxf(sacc[j][0], sacc[j][1]));
            mx1 = fmaxf(mx1, fmaxf(sacc[j][2], sacc[j][3]));
        }
        mx0 = fmaxf(mx0, __shfl_xor_sync(0xffffffffu, mx0, 1));
        mx0 = fmaxf(mx0, __shfl_xor_sync(0xffffffffu, mx0, 2));
        mx1 = fmaxf(mx1, __shfl_xor_sync(0xffffffffu, mx1, 1));
        mx1 = fmaxf(mx1, __shfl_xor_sync(0xffffffffu, mx1, 2));
        float mn0 = fmaxf(mst0, mx0), mn1 = fmaxf(mst1, mx1);
        float f0 = __expf(mst0 - mn0), f1 = __expf(mst1 - mn1);
        float sum0 = 0.f, sum1 = 0.f;
        int prow0 = arow0, prow1 = arow1;
#pragma unroll
        for (int j = 0; j < 8; j++) {
            int cb = j * 8 + 2 * lc;
            float p0 = __expf(sacc[j][0] - mn0);
            float p1 = __expf(sacc[j][1] - mn0);
            float p2 = __expf(sacc[j][2] - mn1);
            float p3 = __expf(sacc[j][3] - mn1);
            sum0 += p0 + p1; sum1 += p2 + p3;
            Ps[prow0 + cb] = f2tf(p0); Ps[prow0 + cb + 1] = f2tf(p1);
            Ps[prow1 + cb] = f2tf(p2); Ps[prow1 + cb + 1] = f2tf(p3);
        }
        sum0 += __shfl_xor_sync(0xffffffffu, sum0, 1);
        sum0 += __shfl_xor_sync(0xffffffffu, sum0, 2);
        sum1 += __shfl_xor_sync(0xffffffffu, sum1, 1);
        sum1 += __shfl_xor_sync(0xffffffffu, sum1, 2);
        lst0 = lst0 * f0 + sum0;  lst1 = lst1 * f1 + sum1;
        mst0 = mn0;  mst1 = mn1;
#pragma unroll
        for (int j = 0; j < 8; j++) {
            o[j][0] *= f0; o[j][1] *= f0; o[j][2] *= f1; o[j][3] *= f1;
        }
        __syncwarp();

        // ---- PV MMA: o += P(16 x 64) x V(64 x 64) ----
#pragma unroll
        for (int kk = 0; kk < 64; kk += 8) {
            uint32_t a0 = Ps[arow0 + kk + lc];
            uint32_t a1 = Ps[arow1 + kk + lc];
            uint32_t a2 = Ps[arow0 + kk + lc + 4];
            uint32_t a3 = Ps[arow1 + kk + lc + 4];
#pragma unroll
            for (int jd = 0; jd < 8; jd++) {
                uint32_t b0 = Vs[(kk + lc) * 72 + jd * 8 + lr];
                uint32_t b1 = Vs[(kk + lc + 4) * 72 + jd * 8 + lr];
                mma_tf32(o[jd], a0, a1, a2, a3, b0, b1);
            }
        }
    }

    // ---- normalize and write attn_vec (tf32-rounded for k_out) ----
    float inv0 = 1.0f / lst0, inv1 = 1.0f / lst1;
    float* outp = g_av + ((size_t)b * QLEN + m0) * DM + h * DH;
#pragma unroll
    for (int jd = 0; jd < 8; jd++) {
        int cb = jd * 8 + 2 * lc;
        *(float2*)(outp + (size_t)(w * 16 + lr) * DM + cb) =
            make_float2(f2tf_f(o[jd][0] * inv0), f2tf_f(o[jd][1] * inv0));
        *(float2*)(outp + (size_t)(w * 16 + 8 + lr) * DM + cb) =
            make_float2(f2tf_f(o[jd][2] * inv1), f2tf_f(o[jd][3] * inv1));
    }
}

// ---------------- out = attn_vec . Wo^T ----------------
__global__ __launch_bounds__(256) void k_out(const float* __restrict__ Wo,
                                             float* __restrict__ out)
{
    const float* A = g_av + (size_t)blockIdx.y * 128 * DM;
    const float* B = Wo + (size_t)blockIdx.x * 128 * DM;
    float* C = out + (size_t)blockIdx.y * 128 * DM + blockIdx.x * 128;

    __shared__ uint32_t As[2][128][PAD16], Bs[2][128][PAD16];
    float acc[4][4][4];
#pragma unroll
    for (int i = 0; i < 4; i++)
#pragma unroll
        for (int j = 0; j < 4; j++)
#pragma unroll
            for (int k = 0; k < 4; k++) acc[i][j][k] = 0.f;

    gemm_db<false, true>(A, DM, B, DM, DM / 16, acc, As, Bs);
    store_tile<false>(C, DM, acc);
}

// ---------------- launch ----------------
extern "C" void kernel_launch(void* const* d_in, const int* in_sizes, int n_in,
                              void* d_out, int out_size)
{
    (void)in_sizes; (void)n_in; (void)out_size;
    const float* x   = (const float*)d_in[0];
    const float* mem = (const float*)d_in[1];
    const float* pos = (const float*)d_in[2];
    // d_in[3] = attn_mask (unused; mask derived analytically)
    const float* Wq  = (const float*)d_in[4];
    const float* Wk  = (const float*)d_in[5];
    const float* Wv  = (const float*)d_in[6];
    const float* Wr  = (const float*)d_in[7];
    const float* Wo  = (const float*)d_in[8];
    const float* bw  = (const float*)d_in[9];   // r_w_bias [16,64]
    const float* br  = (const float*)d_in[10];  // r_r_bias [16,64]
    float* out = (float*)d_out;

    static bool attr_done = false;
    if (!attr_done) {
        cudaFuncSetAttribute(k_flash, cudaFuncAttributeMaxDynamicSharedMemorySize,
                             FLASH_SMEM);
        attr_done = true;
    }

    // 1. all projections (q dual-bias pre-scaled, k, v, r), flat grid
    k_proj_all<<<dim3(8, 96), 256>>>(x, mem, pos, Wq, Wk, Wv, Wr, bw, br);
    // 2. BD (shifted store, banded tiles)
    k_bd<<<dim3(16, 8, 32), 256>>>();
    // 3. fused score + softmax + PV
    k_flash<<<dim3(8, 32), 256, FLASH_SMEM>>>();
    // 4. out = attn_vec . Wo^T
    k_out<<<dim3(8, 16), 256>>>(Wo, out);
}